// round 6
// baseline (speedup 1.0000x reference)
#include <cuda_runtime.h>
#include <cuda_bf16.h>
#include <cstdint>
#include <math.h>

#define NTOT 65536
#define BG   64
#define NPG  1024
#define ETOT 1048576
#define EPG  (ETOT / BG)     // 16384 edges per graph (edge e -> graph e/EPG)
#define DD   128
#define KK   512             // NPG/2

// ---------------- scratch (device globals: allocation-free) ----------------
__device__ float g_h[(size_t)NTOT * DD];      // agg = A_hat @ x
__device__ float g_o[(size_t)NTOT * DD];      // relu(conv output)
__device__ float g_dinv[NTOT];
__device__ float g_score[NTOT];
__device__ float g_pinv;
__device__ int   g_off[NTOT + 1];             // global CSR offsets (by dst)
__device__ int2  g_epack[ETOT];               // {src_local, norm bits} grouped by dst

// ========== fused per-graph CSR build + (block 0) p-norm ==========
__global__ __launch_bounds__(512) void k_build(const int* __restrict__ ei,
                                               const float* __restrict__ ew,
                                               const float* __restrict__ p) {
    __shared__ float sdeg[NPG];
    __shared__ int   scnt[NPG];
    __shared__ int   soff[NPG];
    __shared__ int   scur[NPG];
    __shared__ int   s2[512];

    int g = blockIdx.x;
    int t = threadIdx.x;
    int base_e = g * EPG;
    int base_n = g * NPG;
    const int* src = ei;
    const int* dst = ei + ETOT;

    if (g == 0 && t < 32) {   // p norm (one warp, overlapped with init)
        float4 pv = ((const float4*)p)[t];
        float pp = pv.x * pv.x + pv.y * pv.y + pv.z * pv.z + pv.w * pv.w;
        #pragma unroll
        for (int off = 16; off > 0; off >>= 1) pp += __shfl_xor_sync(0xFFFFFFFFu, pp, off);
        if (t == 0) g_pinv = rsqrtf(pp);
    }

    #pragma unroll
    for (int i = t; i < NPG; i += 512) { sdeg[i] = 1.0f; scnt[i] = 0; }
    __syncthreads();

    for (int e = t; e < EPG; e += 512) {
        int d = dst[base_e + e] - base_n;
        atomicAdd(&sdeg[d], ew[base_e + e]);
        atomicAdd(&scnt[d], 1);
    }
    __syncthreads();

    #pragma unroll
    for (int i = t; i < NPG; i += 512)
        sdeg[i] = rsqrtf(fmaxf(sdeg[i], 1e-12f));
    __syncthreads();

    int c0 = scnt[2 * t], c1 = scnt[2 * t + 1];
    int pairsum = c0 + c1;
    s2[t] = pairsum;
    __syncthreads();
    for (int d = 1; d < 512; d <<= 1) {
        int u = (t >= d) ? s2[t - d] : 0;
        __syncthreads(); s2[t] += u; __syncthreads();
    }
    int excl = s2[t] - pairsum;
    soff[2 * t]     = excl;
    soff[2 * t + 1] = excl + c0;
    scur[2 * t]     = excl;
    scur[2 * t + 1] = excl + c0;
    __syncthreads();

    #pragma unroll
    for (int i = t; i < NPG; i += 512) {
        g_dinv[base_n + i] = sdeg[i];
        g_off[base_n + i]  = base_e + soff[i];
    }
    if (g == 0 && t == 0) g_off[NTOT] = ETOT;

    for (int e = t; e < EPG; e += 512) {
        int s = src[base_e + e] - base_n;
        int d = dst[base_e + e] - base_n;
        float nrm = sdeg[s] * ew[base_e + e] * sdeg[d];
        int pos = atomicAdd(&scur[d], 1);
        g_epack[base_e + pos] = make_int2(s, __float_as_int(nrm));
    }
}

// ========== smem-staged gather, uniform-broadcast edge loads (no shfl) ==========
#define GSM_BYTES (NPG * 32 * 4)    // xs[1024][32] floats = 128 KB

__global__ __launch_bounds__(512, 1) void k_gather_sm(const float* __restrict__ x) {
    extern __shared__ float xs[];   // [1024][32] pitch 32; lane==col: conflict-free
    int g = blockIdx.x >> 2;
    int q = blockIdx.x & 3;
    int base_n = g * NPG;
    int base_e = g * EPG;
    int t = threadIdx.x;
    int w = t >> 5;
    int lane = t & 31;

    for (int i = t; i < NPG * 8; i += 512) {
        int r = i >> 3, c4 = i & 7;
        float4 v = *(const float4*)&x[(size_t)(base_n + r) * DD + q * 32 + c4 * 4];
        float* dp = &xs[r * 32 + c4 * 4];
        dp[0] = v.x; dp[1] = v.y; dp[2] = v.z; dp[3] = v.w;
    }
    __syncthreads();

    const int2* ep = g_epack + base_e;
    for (int node = w; node < NPG; node += 16) {
        int gnode = base_n + node;
        float di = g_dinv[gnode];
        float acc = di * di * xs[node * 32 + lane];

        int i0 = g_off[gnode] - base_e;
        int i1 = g_off[gnode + 1] - base_e;
        #pragma unroll 4
        for (int i = i0; i < i1; i++) {
            int2 pk = ep[i];                        // uniform across warp -> broadcast
            acc += __int_as_float(pk.y) * xs[pk.x * 32 + lane];
        }
        g_h[(size_t)gnode * DD + q * 32 + lane] = acc;
    }
}

// ========== tensor-core GEMM (mma.sync bf16-split, ldmatrix): relu(agg@W+b), score ==========
#define AP 136                                   // bf16 pitch: 272B -> LDSM conflict-free
#define SM_A_HI 0
#define SM_A_LO (128 * AP)
#define SM_B_HI (2 * 128 * AP)
#define SM_B_LO (3 * 128 * AP)
#define SM_F_OFF (4 * 128 * AP * 2)              // byte offset of float area
#define GTC_SMEM (SM_F_OFF + 2 * DD * 4)

__device__ __forceinline__ void bf16_split(float v, __nv_bfloat16& hi, __nv_bfloat16& lo) {
    hi = __float2bfloat16_rn(v);
    lo = __float2bfloat16_rn(v - __bfloat162float(hi));
}

__device__ __forceinline__ void ldsm_x4(uint32_t& r0, uint32_t& r1, uint32_t& r2,
                                        uint32_t& r3, uint32_t addr) {
    asm volatile("ldmatrix.sync.aligned.m8n8.x4.shared.b16 {%0,%1,%2,%3}, [%4];"
                 : "=r"(r0), "=r"(r1), "=r"(r2), "=r"(r3) : "r"(addr));
}

__device__ __forceinline__ void mma_bf16(float* c, uint32_t a0, uint32_t a1, uint32_t a2,
                                         uint32_t a3, uint32_t b0, uint32_t b1) {
    asm volatile(
        "mma.sync.aligned.m16n8k16.row.col.f32.bf16.bf16.f32 "
        "{%0,%1,%2,%3}, {%4,%5,%6,%7}, {%8,%9}, {%0,%1,%2,%3};"
        : "+f"(c[0]), "+f"(c[1]), "+f"(c[2]), "+f"(c[3])
        : "r"(a0), "r"(a1), "r"(a2), "r"(a3), "r"(b0), "r"(b1));
}

__global__ __launch_bounds__(256, 1) void k_gemm_mma(const float* __restrict__ W,
                                                     const float* __restrict__ bvec,
                                                     const float* __restrict__ pvec) {
    extern __shared__ __nv_bfloat16 smb[];
    __nv_bfloat16* Ah = smb + SM_A_HI;
    __nv_bfloat16* Al = smb + SM_A_LO;
    __nv_bfloat16* Bh = smb + SM_B_HI;
    __nv_bfloat16* Bl = smb + SM_B_LO;
    float* bs = (float*)((char*)smb + SM_F_OFF);
    float* ps = bs + DD;

    int tid = threadIdx.x;
    int rb  = blockIdx.x * 128;

    // stage A (g_h rows) hi/lo
    for (int i = tid; i < 128 * 32; i += 256) {
        int r = i >> 5, q = i & 31;
        float4 v = *(const float4*)&g_h[(size_t)(rb + r) * DD + q * 4];
        __nv_bfloat16 h0, l0, h1, l1, h2, l2, h3, l3;
        bf16_split(v.x, h0, l0); bf16_split(v.y, h1, l1);
        bf16_split(v.z, h2, l2); bf16_split(v.w, h3, l3);
        __nv_bfloat16* ah = &Ah[r * AP + q * 4];
        __nv_bfloat16* al = &Al[r * AP + q * 4];
        ah[0] = h0; ah[1] = h1; ah[2] = h2; ah[3] = h3;
        al[0] = l0; al[1] = l1; al[2] = l2; al[3] = l3;
    }
    // stage B = W^T ([n][k]) hi/lo
    for (int i = tid; i < 128 * 32; i += 256) {
        int k = i >> 5, q = i & 31;
        float4 v = *(const float4*)&W[(size_t)k * DD + q * 4];
        float vv[4] = {v.x, v.y, v.z, v.w};
        #pragma unroll
        for (int j = 0; j < 4; j++) {
            __nv_bfloat16 hi, lo;
            bf16_split(vv[j], hi, lo);
            Bh[(q * 4 + j) * AP + k] = hi;
            Bl[(q * 4 + j) * AP + k] = lo;
        }
    }
    if (tid < DD) { bs[tid] = bvec[tid]; ps[tid] = pvec[tid]; }
    __syncthreads();

    int w = tid >> 5;
    int l = tid & 31;
    int qr = l >> 2;
    int qc = l & 3;

    float acc[16][4];
    #pragma unroll
    for (int t = 0; t < 16; t++)
        #pragma unroll
        for (int j = 0; j < 4; j++) acc[t][j] = 0.0f;

    // ldmatrix lane addresses
    // A x4: lanes 0-15 rows (w*16 + l&15) at k-half 0; lanes 16-31 same rows k-half 1
    uint32_t aRowOff = (uint32_t)(((w * 16 + (l & 15)) * AP + ((l >> 4) << 3)) * 2);
    uint32_t sAh = (uint32_t)__cvta_generic_to_shared(Ah) + aRowOff;
    uint32_t sAl = (uint32_t)__cvta_generic_to_shared(Al) + aRowOff;
    // B x4: group g=l>>3: n-half = g>>1, k-half = g&1, row = l&7
    uint32_t bRowOff = (uint32_t)(((((l >> 4) << 3) + (l & 7)) * AP + (((l >> 3) & 1) << 3)) * 2);
    uint32_t sBh = (uint32_t)__cvta_generic_to_shared(Bh) + bRowOff;
    uint32_t sBl = (uint32_t)__cvta_generic_to_shared(Bl) + bRowOff;

    #pragma unroll
    for (int ks = 0; ks < 8; ks++) {
        uint32_t kb = (uint32_t)(ks * 32);       // 16 bf16 = 32 bytes
        uint32_t ah0, ah1, ah2, ah3, al0, al1, al2, al3;
        ldsm_x4(ah0, ah1, ah2, ah3, sAh + kb);
        ldsm_x4(al0, al1, al2, al3, sAl + kb);

        #pragma unroll
        for (int tp = 0; tp < 8; tp++) {
            uint32_t tb = (uint32_t)(tp * 16 * AP * 2) + kb;
            uint32_t bh0, bh1, bh2, bh3, bl0, bl1, bl2, bl3;
            ldsm_x4(bh0, bh1, bh2, bh3, sBh + tb);
            ldsm_x4(bl0, bl1, bl2, bl3, sBl + tb);
            mma_bf16(acc[2 * tp],     ah0, ah1, ah2, ah3, bh0, bh1);
            mma_bf16(acc[2 * tp],     ah0, ah1, ah2, ah3, bl0, bl1);
            mma_bf16(acc[2 * tp],     al0, al1, al2, al3, bh0, bh1);
            mma_bf16(acc[2 * tp + 1], ah0, ah1, ah2, ah3, bh2, bh3);
            mma_bf16(acc[2 * tp + 1], ah0, ah1, ah2, ah3, bl2, bl3);
            mma_bf16(acc[2 * tp + 1], al0, al1, al2, al3, bh2, bh3);
        }
    }

    // epilogue: bias + relu + store g_o + score
    int r0 = rb + w * 16 + qr;
    int r1 = r0 + 8;
    float s0 = 0.0f, s1 = 0.0f;
    #pragma unroll
    for (int t = 0; t < 16; t++) {
        int c0 = t * 8 + qc * 2;
        float b0 = bs[c0], b1 = bs[c0 + 1];
        float p0 = ps[c0], p1 = ps[c0 + 1];
        float v00 = fmaxf(acc[t][0] + b0, 0.0f);
        float v01 = fmaxf(acc[t][1] + b1, 0.0f);
        float v10 = fmaxf(acc[t][2] + b0, 0.0f);
        float v11 = fmaxf(acc[t][3] + b1, 0.0f);
        *(float2*)&g_o[(size_t)r0 * DD + c0] = make_float2(v00, v01);
        *(float2*)&g_o[(size_t)r1 * DD + c0] = make_float2(v10, v11);
        s0 += v00 * p0 + v01 * p1;
        s1 += v10 * p0 + v11 * p1;
    }
    s0 += __shfl_xor_sync(0xFFFFFFFFu, s0, 1);
    s0 += __shfl_xor_sync(0xFFFFFFFFu, s0, 2);
    s1 += __shfl_xor_sync(0xFFFFFFFFu, s1, 1);
    s1 += __shfl_xor_sync(0xFFFFFFFFu, s1, 2);
    if (qc == 0) {
        float pin = g_pinv;
        g_score[r0] = s0 * pin;
        g_score[r1] = s1 * pin;
    }
}

// ---------------- top-K threshold + weighted mean (order-invariant) ----------------
__global__ void k_pool(float* __restrict__ out) {
    __shared__ float s_sc[NPG];
    __shared__ float s_sort[NPG];
    __shared__ float s_w[NPG];
    __shared__ float s_part[8 * DD];
    __shared__ int   s_cnt;

    int g = blockIdx.x;
    int t = threadIdx.x;
    int base = g * NPG;

    float sc = g_score[base + t];
    s_sc[t] = sc; s_sort[t] = sc;
    if (t == 0) s_cnt = 0;
    __syncthreads();

    for (int k = 2; k <= NPG; k <<= 1) {
        for (int j = k >> 1; j > 0; j >>= 1) {
            int ixj = t ^ j;
            if (ixj > t) {
                float a = s_sort[t], b = s_sort[ixj];
                bool up = ((t & k) == 0);
                if ((a > b) == up) { s_sort[t] = b; s_sort[ixj] = a; }
            }
            __syncthreads();
        }
    }
    float thr = s_sort[NPG - KK];
    __syncthreads();

    int isgt = (sc > thr);
    if (isgt) atomicAdd(&s_cnt, 1);
    __syncthreads();
    int need_eq = KK - s_cnt;

    float wgt = 0.0f;
    if (isgt) {
        wgt = tanhf(sc);
    } else if (sc == thr) {
        int r = 0;
        for (int j = 0; j < t; j++) if (s_sc[j] == thr) r++;
        if (r < need_eq) wgt = tanhf(sc);
    }
    s_w[t] = wgt;
    __syncthreads();

    int grp = t >> 7, c = t & 127;
    float part = 0.0f;
    for (int n = grp; n < NPG; n += 8) {
        float wn = s_w[n];
        if (wn != 0.0f) part += wn * g_o[(size_t)(base + n) * DD + c];
    }
    s_part[grp * DD + c] = part;
    __syncthreads();

    if (t < DD) {
        float s = 0.0f;
        #pragma unroll
        for (int q = 0; q < 8; q++) s += s_part[q * DD + t];
        out[g * DD + t] = s * (1.0f / (float)KK);
    }
}

// ---------------- launch ----------------
extern "C" void kernel_launch(void* const* d_in, const int* in_sizes, int n_in,
                              void* d_out, int out_size) {
    const float* x  = (const float*)d_in[0];
    const float* ew = (const float*)d_in[1];
    const float* W  = (const float*)d_in[2];
    const float* b  = (const float*)d_in[3];
    const float* p  = (const float*)d_in[4];
    const int*   ei = (const int*)d_in[5];
    float* out = (float*)d_out;

    static int s_attr_done = 0;
    if (!s_attr_done) {
        cudaFuncSetAttribute(k_gemm_mma, cudaFuncAttributeMaxDynamicSharedMemorySize, GTC_SMEM);
        cudaFuncSetAttribute(k_gather_sm, cudaFuncAttributeMaxDynamicSharedMemorySize, GSM_BYTES);
        s_attr_done = 1;
    }

    k_build<<<BG, 512>>>(ei, ew, p);
    k_gather_sm<<<BG * 4, 512, GSM_BYTES>>>(x);
    k_gemm_mma<<<NTOT / 128, 256, GTC_SMEM>>>(W, b, p);
    k_pool<<<BG, NPG>>>(out);
}

// round 7
// speedup vs baseline: 1.8063x; 1.8063x over previous
#include <cuda_runtime.h>
#include <cuda_bf16.h>
#include <cstdint>
#include <math.h>

#define NTOT 65536
#define BG   64
#define NPG  1024
#define ETOT 1048576
#define EPG  (ETOT / BG)     // 16384 edges per graph
#define DD   128
#define KK   512             // NPG/2

// ---------------- scratch (device globals: allocation-free) ----------------
__device__ float g_h[(size_t)NTOT * DD];      // agg = A_hat @ x
__device__ float g_o[(size_t)NTOT * DD];      // relu(conv output)
__device__ float g_dinv[NTOT];
__device__ float g_scorep[2 * NTOT];          // per-half score partials
__device__ float g_pinv;
__device__ int   g_off[NTOT + 1];
__device__ int2  g_epack[ETOT];               // {src_local, norm bits} grouped by dst

// ========== fused per-graph CSR build + (block 0) p-norm ==========
__global__ __launch_bounds__(512) void k_build(const int* __restrict__ ei,
                                               const float* __restrict__ ew,
                                               const float* __restrict__ p) {
    __shared__ float sdeg[NPG];
    __shared__ int   scnt[NPG];
    __shared__ int   soff[NPG];
    __shared__ int   scur[NPG];
    __shared__ int   s2[512];

    int g = blockIdx.x;
    int t = threadIdx.x;
    int base_e = g * EPG;
    int base_n = g * NPG;
    const int* src = ei;
    const int* dst = ei + ETOT;

    if (g == 0 && t < 32) {
        float4 pv = ((const float4*)p)[t];
        float pp = pv.x * pv.x + pv.y * pv.y + pv.z * pv.z + pv.w * pv.w;
        #pragma unroll
        for (int off = 16; off > 0; off >>= 1) pp += __shfl_xor_sync(0xFFFFFFFFu, pp, off);
        if (t == 0) g_pinv = rsqrtf(pp);
    }

    #pragma unroll
    for (int i = t; i < NPG; i += 512) { sdeg[i] = 1.0f; scnt[i] = 0; }
    __syncthreads();

    for (int e = t; e < EPG; e += 512) {
        int d = dst[base_e + e] - base_n;
        atomicAdd(&sdeg[d], ew[base_e + e]);
        atomicAdd(&scnt[d], 1);
    }
    __syncthreads();

    #pragma unroll
    for (int i = t; i < NPG; i += 512)
        sdeg[i] = rsqrtf(fmaxf(sdeg[i], 1e-12f));
    __syncthreads();

    int c0 = scnt[2 * t], c1 = scnt[2 * t + 1];
    int pairsum = c0 + c1;
    s2[t] = pairsum;
    __syncthreads();
    for (int d = 1; d < 512; d <<= 1) {
        int u = (t >= d) ? s2[t - d] : 0;
        __syncthreads(); s2[t] += u; __syncthreads();
    }
    int excl = s2[t] - pairsum;
    soff[2 * t]     = excl;
    soff[2 * t + 1] = excl + c0;
    scur[2 * t]     = excl;
    scur[2 * t + 1] = excl + c0;
    __syncthreads();

    #pragma unroll
    for (int i = t; i < NPG; i += 512) {
        g_dinv[base_n + i] = sdeg[i];
        g_off[base_n + i]  = base_e + soff[i];
    }
    if (g == 0 && t == 0) g_off[NTOT] = ETOT;

    for (int e = t; e < EPG; e += 512) {
        int s = src[base_e + e] - base_n;
        int d = dst[base_e + e] - base_n;
        float nrm = sdeg[s] * ew[base_e + e] * sdeg[d];
        int pos = atomicAdd(&scur[d], 1);
        g_epack[base_e + pos] = make_int2(s, __float_as_int(nrm));   // src LOCAL
    }
}

// ========== gather (R4-proven): warp per node, coalesced epack + shfl ==========
__global__ void k_gather(const float* __restrict__ x) {
    int gt   = blockIdx.x * blockDim.x + threadIdx.x;
    int node = gt >> 5;
    int lane = gt & 31;
    if (node >= NTOT) return;
    int base_n = node & ~(NPG - 1);              // graph base (local src -> global)

    const float4* x4 = (const float4*)x;
    float di = g_dinv[node];
    float c  = di * di;
    float4 xv = x4[(size_t)node * 32 + lane];
    float4 acc = make_float4(c * xv.x, c * xv.y, c * xv.z, c * xv.w);

    int i0 = g_off[node], i1 = g_off[node + 1];
    for (int base = i0; base < i1; base += 32) {
        int nload = i1 - base; if (nload > 32) nload = 32;
        int2 pk = make_int2(0, 0);
        if (lane < nload) pk = g_epack[base + lane];
        int j = 0;
        for (; j + 4 <= nload; j += 4) {
            #pragma unroll
            for (int u = 0; u < 4; u++) {
                int   s  = base_n + __shfl_sync(0xFFFFFFFFu, pk.x, j + u);
                float nm = __int_as_float(__shfl_sync(0xFFFFFFFFu, pk.y, j + u));
                float4 v = x4[(size_t)s * 32 + lane];
                acc.x += nm * v.x; acc.y += nm * v.y;
                acc.z += nm * v.z; acc.w += nm * v.w;
            }
        }
        for (; j < nload; j++) {
            int   s  = base_n + __shfl_sync(0xFFFFFFFFu, pk.x, j);
            float nm = __int_as_float(__shfl_sync(0xFFFFFFFFu, pk.y, j));
            float4 v = x4[(size_t)s * 32 + lane];
            acc.x += nm * v.x; acc.y += nm * v.y;
            acc.z += nm * v.z; acc.w += nm * v.w;
        }
    }
    ((float4*)g_h)[(size_t)node * 32 + lane] = acc;
}

// ========== tensor-core GEMM, N-split for 2 CTAs/SM: relu(agg@W+b), score partials ==========
#define AP 132
#define NH 64                                  // cols per CTA
#define SM_A_HI 0
#define SM_A_LO (128 * AP)
#define SM_B_HI (2 * 128 * AP)
#define SM_B_LO (2 * 128 * AP + NH * AP)
#define SM_F_OFF ((2 * 128 + 2 * NH) * AP * 2) // byte offset of float area
#define GTC_SMEM (SM_F_OFF + 2 * NH * 4)

__device__ __forceinline__ void bf16_split(float v, __nv_bfloat16& hi, __nv_bfloat16& lo) {
    hi = __float2bfloat16_rn(v);
    lo = __float2bfloat16_rn(v - __bfloat162float(hi));
}

__device__ __forceinline__ void mma_bf16(float* c, uint32_t a0, uint32_t a1, uint32_t a2,
                                         uint32_t a3, uint32_t b0, uint32_t b1) {
    asm volatile(
        "mma.sync.aligned.m16n8k16.row.col.f32.bf16.bf16.f32 "
        "{%0,%1,%2,%3}, {%4,%5,%6,%7}, {%8,%9}, {%0,%1,%2,%3};"
        : "+f"(c[0]), "+f"(c[1]), "+f"(c[2]), "+f"(c[3])
        : "r"(a0), "r"(a1), "r"(a2), "r"(a3), "r"(b0), "r"(b1));
}

__global__ __launch_bounds__(256, 2) void k_gemm_mma(const float* __restrict__ W,
                                                     const float* __restrict__ bvec,
                                                     const float* __restrict__ pvec) {
    extern __shared__ __nv_bfloat16 smb[];
    __nv_bfloat16* Ah = smb + SM_A_HI;
    __nv_bfloat16* Al = smb + SM_A_LO;
    __nv_bfloat16* Bh = smb + SM_B_HI;
    __nv_bfloat16* Bl = smb + SM_B_LO;
    float* bs = (float*)((char*)smb + SM_F_OFF);
    float* ps = bs + NH;

    int tid = threadIdx.x;
    int rb  = (blockIdx.x >> 1) * 128;
    int nh  = blockIdx.x & 1;                  // column half

    // stage A (g_h rows) hi/lo
    for (int i = tid; i < 128 * 32; i += 256) {
        int r = i >> 5, q = i & 31;
        float4 v = *(const float4*)&g_h[(size_t)(rb + r) * DD + q * 4];
        __nv_bfloat16 h0, l0, h1, l1, h2, l2, h3, l3;
        bf16_split(v.x, h0, l0); bf16_split(v.y, h1, l1);
        bf16_split(v.z, h2, l2); bf16_split(v.w, h3, l3);
        __nv_bfloat16* ah = &Ah[r * AP + q * 4];
        __nv_bfloat16* al = &Al[r * AP + q * 4];
        ah[0] = h0; ah[1] = h1; ah[2] = h2; ah[3] = h3;
        al[0] = l0; al[1] = l1; al[2] = l2; al[3] = l3;
    }
    // stage B-half = W^T rows [nh*64, nh*64+64)
    for (int i = tid; i < 128 * 16; i += 256) {
        int k = i >> 4, q = i & 15;
        float4 v = *(const float4*)&W[(size_t)k * DD + nh * NH + q * 4];
        float vv[4] = {v.x, v.y, v.z, v.w};
        #pragma unroll
        for (int j = 0; j < 4; j++) {
            __nv_bfloat16 hi, lo;
            bf16_split(vv[j], hi, lo);
            Bh[(q * 4 + j) * AP + k] = hi;
            Bl[(q * 4 + j) * AP + k] = lo;
        }
    }
    if (tid < NH) { bs[tid] = bvec[nh * NH + tid]; ps[tid] = pvec[nh * NH + tid]; }
    __syncthreads();

    int w  = tid >> 5;
    int l  = tid & 31;
    int qr = l >> 2;
    int qc = l & 3;

    float acc[8][4];
    #pragma unroll
    for (int t = 0; t < 8; t++)
        #pragma unroll
        for (int j = 0; j < 4; j++) acc[t][j] = 0.0f;

    const __nv_bfloat16* arow0  = Ah + (w * 16 + qr) * AP;
    const __nv_bfloat16* arow1  = arow0 + 8 * AP;
    const __nv_bfloat16* alrow0 = Al + (w * 16 + qr) * AP;
    const __nv_bfloat16* alrow1 = alrow0 + 8 * AP;

    #pragma unroll
    for (int ks = 0; ks < 8; ks++) {
        int k0 = ks * 16;
        uint32_t ah0 = *(const uint32_t*)(arow0  + k0 + qc * 2);
        uint32_t ah1 = *(const uint32_t*)(arow1  + k0 + qc * 2);
        uint32_t ah2 = *(const uint32_t*)(arow0  + k0 + 8 + qc * 2);
        uint32_t ah3 = *(const uint32_t*)(arow1  + k0 + 8 + qc * 2);
        uint32_t al0 = *(const uint32_t*)(alrow0 + k0 + qc * 2);
        uint32_t al1 = *(const uint32_t*)(alrow1 + k0 + qc * 2);
        uint32_t al2 = *(const uint32_t*)(alrow0 + k0 + 8 + qc * 2);
        uint32_t al3 = *(const uint32_t*)(alrow1 + k0 + 8 + qc * 2);

        #pragma unroll
        for (int t = 0; t < 8; t++) {
            const __nv_bfloat16* brow  = Bh + (t * 8 + qr) * AP;
            const __nv_bfloat16* browl = Bl + (t * 8 + qr) * AP;
            uint32_t bh0 = *(const uint32_t*)(brow  + k0 + qc * 2);
            uint32_t bh1 = *(const uint32_t*)(brow  + k0 + 8 + qc * 2);
            uint32_t bl0 = *(const uint32_t*)(browl + k0 + qc * 2);
            uint32_t bl1 = *(const uint32_t*)(browl + k0 + 8 + qc * 2);
            mma_bf16(acc[t], ah0, ah1, ah2, ah3, bh0, bh1);
            mma_bf16(acc[t], ah0, ah1, ah2, ah3, bl0, bl1);
            mma_bf16(acc[t], al0, al1, al2, al3, bh0, bh1);
        }
    }

    // epilogue: bias + relu + store g_o half + score partial
    int r0 = rb + w * 16 + qr;
    int r1 = r0 + 8;
    float s0 = 0.0f, s1 = 0.0f;
    #pragma unroll
    for (int t = 0; t < 8; t++) {
        int cl = t * 8 + qc * 2;
        int cg = nh * NH + cl;
        float b0 = bs[cl], b1 = bs[cl + 1];
        float p0 = ps[cl], p1 = ps[cl + 1];
        float v00 = fmaxf(acc[t][0] + b0, 0.0f);
        float v01 = fmaxf(acc[t][1] + b1, 0.0f);
        float v10 = fmaxf(acc[t][2] + b0, 0.0f);
        float v11 = fmaxf(acc[t][3] + b1, 0.0f);
        *(float2*)&g_o[(size_t)r0 * DD + cg] = make_float2(v00, v01);
        *(float2*)&g_o[(size_t)r1 * DD + cg] = make_float2(v10, v11);
        s0 += v00 * p0 + v01 * p1;
        s1 += v10 * p0 + v11 * p1;
    }
    s0 += __shfl_xor_sync(0xFFFFFFFFu, s0, 1);
    s0 += __shfl_xor_sync(0xFFFFFFFFu, s0, 2);
    s1 += __shfl_xor_sync(0xFFFFFFFFu, s1, 1);
    s1 += __shfl_xor_sync(0xFFFFFFFFu, s1, 2);
    if (qc == 0) {
        g_scorep[2 * r0 + nh] = s0;
        g_scorep[2 * r1 + nh] = s1;
    }
}

// ========== pool: 4-pass radix select threshold + weighted mean ==========
__global__ void k_pool(float* __restrict__ out) {
    __shared__ uint32_t s_u[NPG];
    __shared__ float    s_w[NPG];
    __shared__ int      hist[256];
    __shared__ int      sB, sRem;
    __shared__ float    s_part[8 * DD];

    int g = blockIdx.x;
    int t = threadIdx.x;
    int base = g * NPG;

    float sc = (g_scorep[2 * (base + t)] + g_scorep[2 * (base + t) + 1]) * g_pinv;
    uint32_t u = __float_as_uint(sc);
    u = (u & 0x80000000u) ? ~u : (u | 0x80000000u);   // order-preserving map
    s_u[t] = u;

    bool active = true, sel_gt = false;
    int remaining = KK;

    #pragma unroll
    for (int shift = 24; shift >= 0; shift -= 8) {
        if (t < 256) hist[t] = 0;
        __syncthreads();
        int mybin = (int)((u >> shift) & 0xFFu);
        if (active) atomicAdd(&hist[mybin], 1);
        __syncthreads();
        // suffix sums: hist[b] = count of active with bin >= b
        for (int d = 1; d < 256; d <<= 1) {
            int v = 0;
            if (t < 256) v = hist[t] + ((t + d < 256) ? hist[t + d] : 0);
            __syncthreads();
            if (t < 256) hist[t] = v;
            __syncthreads();
        }
        if (t < 256) {
            int ge = hist[t];
            int gtc = (t == 255) ? 0 : hist[t + 1];
            if (ge >= remaining && gtc < remaining) { sB = t; sRem = remaining - gtc; }
        }
        __syncthreads();
        int B = sB; remaining = sRem;
        if (active) {
            if (mybin > B) { sel_gt = true; active = false; }
            else if (mybin < B) active = false;
        }
        __syncthreads();
    }

    // active <=> u == threshold bits; remaining = #ties included (lowest index first)
    float wgt = 0.0f;
    if (sel_gt) {
        wgt = tanhf(sc);
    } else if (active) {
        uint32_t uth = u;
        int r = 0;
        for (int j = 0; j < t; j++) if (s_u[j] == uth) r++;
        if (r < remaining) wgt = tanhf(sc);
    }
    s_w[t] = wgt;
    __syncthreads();

    int grp = t >> 7, c = t & 127;
    float part = 0.0f;
    for (int n = grp; n < NPG; n += 8) {
        float wn = s_w[n];
        if (wn != 0.0f) part += wn * g_o[(size_t)(base + n) * DD + c];
    }
    s_part[grp * DD + c] = part;
    __syncthreads();

    if (t < DD) {
        float s = 0.0f;
        #pragma unroll
        for (int q = 0; q < 8; q++) s += s_part[q * DD + t];
        out[g * DD + t] = s * (1.0f / (float)KK);
    }
}

// ---------------- launch ----------------
extern "C" void kernel_launch(void* const* d_in, const int* in_sizes, int n_in,
                              void* d_out, int out_size) {
    const float* x  = (const float*)d_in[0];
    const float* ew = (const float*)d_in[1];
    const float* W  = (const float*)d_in[2];
    const float* b  = (const float*)d_in[3];
    const float* p  = (const float*)d_in[4];
    const int*   ei = (const int*)d_in[5];
    float* out = (float*)d_out;

    static int s_attr_done = 0;
    if (!s_attr_done) {
        cudaFuncSetAttribute(k_gemm_mma, cudaFuncAttributeMaxDynamicSharedMemorySize, GTC_SMEM);
        s_attr_done = 1;
    }

    k_build<<<BG, 512>>>(ei, ew, p);
    k_gather<<<(NTOT * 32) / 256, 256>>>(x);
    k_gemm_mma<<<(NTOT / 128) * 2, 256, GTC_SMEM>>>(W, b, p);
    k_pool<<<BG, NPG>>>(out);
}

// round 8
// speedup vs baseline: 1.8218x; 1.0086x over previous
#include <cuda_runtime.h>
#include <cuda_bf16.h>
#include <cstdint>
#include <math.h>

#define NTOT 65536
#define BG   64
#define NPG  1024
#define ETOT 1048576
#define EPG  (ETOT / BG)     // 16384 edges per graph
#define DD   128
#define KK   512             // NPG/2

// ---------------- scratch (device globals: allocation-free) ----------------
__device__ float g_h[(size_t)NTOT * DD];      // agg = A_hat @ x
__device__ float g_o[(size_t)NTOT * DD];      // relu(conv output)
__device__ float g_dinv[NTOT];
__device__ float g_scorep[2 * NTOT];          // per-half score partials
__device__ float g_w[NTOT];                   // pooling weights (tanh or 0)
__device__ float g_pinv;
__device__ int   g_off[NTOT + 1];
__device__ int2  g_epack[ETOT];               // {src_local, norm bits} grouped by dst

// ========== fused per-graph CSR build + (block 0) p-norm ==========
__global__ __launch_bounds__(512) void k_build(const int* __restrict__ ei,
                                               const float* __restrict__ ew,
                                               const float* __restrict__ p) {
    __shared__ float sdeg[NPG];
    __shared__ int   scnt[NPG];
    __shared__ int   soff[NPG];
    __shared__ int   scur[NPG];
    __shared__ int   s2[512];

    int g = blockIdx.x;
    int t = threadIdx.x;
    int base_e = g * EPG;
    int base_n = g * NPG;
    const int* src = ei;
    const int* dst = ei + ETOT;

    if (g == 0 && t < 32) {
        float4 pv = ((const float4*)p)[t];
        float pp = pv.x * pv.x + pv.y * pv.y + pv.z * pv.z + pv.w * pv.w;
        #pragma unroll
        for (int off = 16; off > 0; off >>= 1) pp += __shfl_xor_sync(0xFFFFFFFFu, pp, off);
        if (t == 0) g_pinv = rsqrtf(pp);
    }

    #pragma unroll
    for (int i = t; i < NPG; i += 512) { sdeg[i] = 1.0f; scnt[i] = 0; }
    __syncthreads();

    for (int e = t; e < EPG; e += 512) {
        int d = dst[base_e + e] - base_n;
        atomicAdd(&sdeg[d], ew[base_e + e]);
        atomicAdd(&scnt[d], 1);
    }
    __syncthreads();

    #pragma unroll
    for (int i = t; i < NPG; i += 512)
        sdeg[i] = rsqrtf(fmaxf(sdeg[i], 1e-12f));
    __syncthreads();

    int c0 = scnt[2 * t], c1 = scnt[2 * t + 1];
    int pairsum = c0 + c1;
    s2[t] = pairsum;
    __syncthreads();
    for (int d = 1; d < 512; d <<= 1) {
        int u = (t >= d) ? s2[t - d] : 0;
        __syncthreads(); s2[t] += u; __syncthreads();
    }
    int excl = s2[t] - pairsum;
    soff[2 * t]     = excl;
    soff[2 * t + 1] = excl + c0;
    scur[2 * t]     = excl;
    scur[2 * t + 1] = excl + c0;
    __syncthreads();

    #pragma unroll
    for (int i = t; i < NPG; i += 512) {
        g_dinv[base_n + i] = sdeg[i];
        g_off[base_n + i]  = base_e + soff[i];
    }
    if (g == 0 && t == 0) g_off[NTOT] = ETOT;

    for (int e = t; e < EPG; e += 512) {
        int s = src[base_e + e] - base_n;
        int d = dst[base_e + e] - base_n;
        float nrm = sdeg[s] * ew[base_e + e] * sdeg[d];
        int pos = atomicAdd(&scur[d], 1);
        g_epack[base_e + pos] = make_int2(s, __float_as_int(nrm));   // src LOCAL
    }
}

// ========== gather (proven): warp per node, coalesced epack + shfl ==========
__global__ void k_gather(const float* __restrict__ x) {
    int gt   = blockIdx.x * blockDim.x + threadIdx.x;
    int node = gt >> 5;
    int lane = gt & 31;
    if (node >= NTOT) return;
    int base_n = node & ~(NPG - 1);

    const float4* x4 = (const float4*)x;
    float di = g_dinv[node];
    float c  = di * di;
    float4 xv = x4[(size_t)node * 32 + lane];
    float4 acc = make_float4(c * xv.x, c * xv.y, c * xv.z, c * xv.w);

    int i0 = g_off[node], i1 = g_off[node + 1];
    for (int base = i0; base < i1; base += 32) {
        int nload = i1 - base; if (nload > 32) nload = 32;
        int2 pk = make_int2(0, 0);
        if (lane < nload) pk = g_epack[base + lane];
        int j = 0;
        for (; j + 4 <= nload; j += 4) {
            #pragma unroll
            for (int u = 0; u < 4; u++) {
                int   s  = base_n + __shfl_sync(0xFFFFFFFFu, pk.x, j + u);
                float nm = __int_as_float(__shfl_sync(0xFFFFFFFFu, pk.y, j + u));
                float4 v = x4[(size_t)s * 32 + lane];
                acc.x += nm * v.x; acc.y += nm * v.y;
                acc.z += nm * v.z; acc.w += nm * v.w;
            }
        }
        for (; j < nload; j++) {
            int   s  = base_n + __shfl_sync(0xFFFFFFFFu, pk.x, j);
            float nm = __int_as_float(__shfl_sync(0xFFFFFFFFu, pk.y, j));
            float4 v = x4[(size_t)s * 32 + lane];
            acc.x += nm * v.x; acc.y += nm * v.y;
            acc.z += nm * v.z; acc.w += nm * v.w;
        }
    }
    ((float4*)g_h)[(size_t)node * 32 + lane] = acc;
}

// ========== tensor-core GEMM, N-split for 2 CTAs/SM ==========
#define AP 132
#define NH 64
#define SM_A_HI 0
#define SM_A_LO (128 * AP)
#define SM_B_HI (2 * 128 * AP)
#define SM_B_LO (2 * 128 * AP + NH * AP)
#define SM_F_OFF ((2 * 128 + 2 * NH) * AP * 2)
#define GTC_SMEM (SM_F_OFF + 2 * NH * 4)

__device__ __forceinline__ void bf16_split(float v, __nv_bfloat16& hi, __nv_bfloat16& lo) {
    hi = __float2bfloat16_rn(v);
    lo = __float2bfloat16_rn(v - __bfloat162float(hi));
}

__device__ __forceinline__ void mma_bf16(float* c, uint32_t a0, uint32_t a1, uint32_t a2,
                                         uint32_t a3, uint32_t b0, uint32_t b1) {
    asm volatile(
        "mma.sync.aligned.m16n8k16.row.col.f32.bf16.bf16.f32 "
        "{%0,%1,%2,%3}, {%4,%5,%6,%7}, {%8,%9}, {%0,%1,%2,%3};"
        : "+f"(c[0]), "+f"(c[1]), "+f"(c[2]), "+f"(c[3])
        : "r"(a0), "r"(a1), "r"(a2), "r"(a3), "r"(b0), "r"(b1));
}

__global__ __launch_bounds__(256, 2) void k_gemm_mma(const float* __restrict__ W,
                                                     const float* __restrict__ bvec,
                                                     const float* __restrict__ pvec) {
    extern __shared__ __nv_bfloat16 smb[];
    __nv_bfloat16* Ah = smb + SM_A_HI;
    __nv_bfloat16* Al = smb + SM_A_LO;
    __nv_bfloat16* Bh = smb + SM_B_HI;
    __nv_bfloat16* Bl = smb + SM_B_LO;
    float* bs = (float*)((char*)smb + SM_F_OFF);
    float* ps = bs + NH;

    int tid = threadIdx.x;
    int rb  = (blockIdx.x >> 1) * 128;
    int nh  = blockIdx.x & 1;

    for (int i = tid; i < 128 * 32; i += 256) {
        int r = i >> 5, q = i & 31;
        float4 v = *(const float4*)&g_h[(size_t)(rb + r) * DD + q * 4];
        __nv_bfloat16 h0, l0, h1, l1, h2, l2, h3, l3;
        bf16_split(v.x, h0, l0); bf16_split(v.y, h1, l1);
        bf16_split(v.z, h2, l2); bf16_split(v.w, h3, l3);
        __nv_bfloat16* ah = &Ah[r * AP + q * 4];
        __nv_bfloat16* al = &Al[r * AP + q * 4];
        ah[0] = h0; ah[1] = h1; ah[2] = h2; ah[3] = h3;
        al[0] = l0; al[1] = l1; al[2] = l2; al[3] = l3;
    }
    for (int i = tid; i < 128 * 16; i += 256) {
        int k = i >> 4, q = i & 15;
        float4 v = *(const float4*)&W[(size_t)k * DD + nh * NH + q * 4];
        float vv[4] = {v.x, v.y, v.z, v.w};
        #pragma unroll
        for (int j = 0; j < 4; j++) {
            __nv_bfloat16 hi, lo;
            bf16_split(vv[j], hi, lo);
            Bh[(q * 4 + j) * AP + k] = hi;
            Bl[(q * 4 + j) * AP + k] = lo;
        }
    }
    if (tid < NH) { bs[tid] = bvec[nh * NH + tid]; ps[tid] = pvec[nh * NH + tid]; }
    __syncthreads();

    int w  = tid >> 5;
    int l  = tid & 31;
    int qr = l >> 2;
    int qc = l & 3;

    float acc[8][4];
    #pragma unroll
    for (int t = 0; t < 8; t++)
        #pragma unroll
        for (int j = 0; j < 4; j++) acc[t][j] = 0.0f;

    const __nv_bfloat16* arow0  = Ah + (w * 16 + qr) * AP;
    const __nv_bfloat16* arow1  = arow0 + 8 * AP;
    const __nv_bfloat16* alrow0 = Al + (w * 16 + qr) * AP;
    const __nv_bfloat16* alrow1 = alrow0 + 8 * AP;

    #pragma unroll
    for (int ks = 0; ks < 8; ks++) {
        int k0 = ks * 16;
        uint32_t ah0 = *(const uint32_t*)(arow0  + k0 + qc * 2);
        uint32_t ah1 = *(const uint32_t*)(arow1  + k0 + qc * 2);
        uint32_t ah2 = *(const uint32_t*)(arow0  + k0 + 8 + qc * 2);
        uint32_t ah3 = *(const uint32_t*)(arow1  + k0 + 8 + qc * 2);
        uint32_t al0 = *(const uint32_t*)(alrow0 + k0 + qc * 2);
        uint32_t al1 = *(const uint32_t*)(alrow1 + k0 + qc * 2);
        uint32_t al2 = *(const uint32_t*)(alrow0 + k0 + 8 + qc * 2);
        uint32_t al3 = *(const uint32_t*)(alrow1 + k0 + 8 + qc * 2);

        #pragma unroll
        for (int t = 0; t < 8; t++) {
            const __nv_bfloat16* brow  = Bh + (t * 8 + qr) * AP;
            const __nv_bfloat16* browl = Bl + (t * 8 + qr) * AP;
            uint32_t bh0 = *(const uint32_t*)(brow  + k0 + qc * 2);
            uint32_t bh1 = *(const uint32_t*)(brow  + k0 + 8 + qc * 2);
            uint32_t bl0 = *(const uint32_t*)(browl + k0 + qc * 2);
            uint32_t bl1 = *(const uint32_t*)(browl + k0 + 8 + qc * 2);
            mma_bf16(acc[t], ah0, ah1, ah2, ah3, bh0, bh1);
            mma_bf16(acc[t], ah0, ah1, ah2, ah3, bl0, bl1);
            mma_bf16(acc[t], al0, al1, al2, al3, bh0, bh1);
        }
    }

    int r0 = rb + w * 16 + qr;
    int r1 = r0 + 8;
    float s0 = 0.0f, s1 = 0.0f;
    #pragma unroll
    for (int t = 0; t < 8; t++) {
        int cl = t * 8 + qc * 2;
        int cg = nh * NH + cl;
        float b0 = bs[cl], b1 = bs[cl + 1];
        float p0 = ps[cl], p1 = ps[cl + 1];
        float v00 = fmaxf(acc[t][0] + b0, 0.0f);
        float v01 = fmaxf(acc[t][1] + b1, 0.0f);
        float v10 = fmaxf(acc[t][2] + b0, 0.0f);
        float v11 = fmaxf(acc[t][3] + b1, 0.0f);
        *(float2*)&g_o[(size_t)r0 * DD + cg] = make_float2(v00, v01);
        *(float2*)&g_o[(size_t)r1 * DD + cg] = make_float2(v10, v11);
        s0 += v00 * p0 + v01 * p1;
        s1 += v10 * p0 + v11 * p1;
    }
    s0 += __shfl_xor_sync(0xFFFFFFFFu, s0, 1);
    s0 += __shfl_xor_sync(0xFFFFFFFFu, s0, 2);
    s1 += __shfl_xor_sync(0xFFFFFFFFu, s1, 1);
    s1 += __shfl_xor_sync(0xFFFFFFFFu, s1, 2);
    if (qc == 0) {
        g_scorep[2 * r0 + nh] = s0;
        g_scorep[2 * r1 + nh] = s1;
    }
}

// ========== select: radix threshold -> weights ==========
__global__ void k_select() {
    __shared__ uint32_t s_u[NPG];
    __shared__ int      hist[256];
    __shared__ int      sB, sRem;

    int g = blockIdx.x;
    int t = threadIdx.x;
    int base = g * NPG;

    float sc = (g_scorep[2 * (base + t)] + g_scorep[2 * (base + t) + 1]) * g_pinv;
    uint32_t u = __float_as_uint(sc);
    u = (u & 0x80000000u) ? ~u : (u | 0x80000000u);
    s_u[t] = u;

    bool active = true, sel_gt = false;
    int remaining = KK;

    #pragma unroll
    for (int shift = 24; shift >= 0; shift -= 8) {
        if (t < 256) hist[t] = 0;
        __syncthreads();
        int mybin = (int)((u >> shift) & 0xFFu);
        if (active) atomicAdd(&hist[mybin], 1);
        __syncthreads();
        for (int d = 1; d < 256; d <<= 1) {
            int v = 0;
            if (t < 256) v = hist[t] + ((t + d < 256) ? hist[t + d] : 0);
            __syncthreads();
            if (t < 256) hist[t] = v;
            __syncthreads();
        }
        if (t < 256) {
            int ge = hist[t];
            int gtc = (t == 255) ? 0 : hist[t + 1];
            if (ge >= remaining && gtc < remaining) { sB = t; sRem = remaining - gtc; }
        }
        __syncthreads();
        int B = sB; remaining = sRem;
        if (active) {
            if (mybin > B) { sel_gt = true; active = false; }
            else if (mybin < B) active = false;
        }
        __syncthreads();
    }

    float wgt = 0.0f;
    if (sel_gt) {
        wgt = tanhf(sc);
    } else if (active) {
        uint32_t uth = u;
        int r = 0;
        for (int j = 0; j < t; j++) if (s_u[j] == uth) r++;
        if (r < remaining) wgt = tanhf(sc);
    }
    g_w[base + t] = wgt;
}

// ========== weighted sum: block = (graph, 32-col quarter) ==========
__global__ __launch_bounds__(512) void k_wsum(float* __restrict__ out) {
    __shared__ float s_w[NPG];
    __shared__ float s_part[16 * 32];

    int g = blockIdx.x >> 2;
    int q = blockIdx.x & 3;
    int base = g * NPG;
    int t = threadIdx.x;
    int lane = t & 31;       // column within quarter
    int grp  = t >> 5;       // 0..15 node group

    for (int i = t; i < NPG; i += 512) s_w[i] = g_w[base + i];
    __syncthreads();

    float part = 0.0f;
    #pragma unroll 4
    for (int n = grp; n < NPG; n += 16) {
        float wn = s_w[n];
        if (wn != 0.0f)
            part += wn * g_o[(size_t)(base + n) * DD + q * 32 + lane];
    }
    s_part[grp * 32 + lane] = part;
    __syncthreads();

    if (t < 32) {
        float s = 0.0f;
        #pragma unroll
        for (int r = 0; r < 16; r++) s += s_part[r * 32 + t];
        out[g * DD + q * 32 + t] = s * (1.0f / (float)KK);
    }
}

// ---------------- launch ----------------
extern "C" void kernel_launch(void* const* d_in, const int* in_sizes, int n_in,
                              void* d_out, int out_size) {
    const float* x  = (const float*)d_in[0];
    const float* ew = (const float*)d_in[1];
    const float* W  = (const float*)d_in[2];
    const float* b  = (const float*)d_in[3];
    const float* p  = (const float*)d_in[4];
    const int*   ei = (const int*)d_in[5];
    float* out = (float*)d_out;

    static int s_attr_done = 0;
    if (!s_attr_done) {
        cudaFuncSetAttribute(k_gemm_mma, cudaFuncAttributeMaxDynamicSharedMemorySize, GTC_SMEM);
        s_attr_done = 1;
    }

    k_build<<<BG, 512>>>(ei, ew, p);
    k_gather<<<(NTOT * 32) / 256, 256>>>(x);
    k_gemm_mma<<<(NTOT / 128) * 2, 256, GTC_SMEM>>>(W, b, p);
    k_select<<<BG, NPG>>>();
    k_wsum<<<BG * 4, 512>>>(out);
}

// round 9
// speedup vs baseline: 1.9463x; 1.0683x over previous
#include <cuda_runtime.h>
#include <cuda_bf16.h>
#include <cstdint>
#include <math.h>

#define NTOT 65536
#define BG   64
#define NPG  1024
#define ETOT 1048576
#define EPG  (ETOT / BG)     // 16384 edges per graph
#define DD   128
#define KK   512             // NPG/2

// ---------------- scratch (device globals: allocation-free) ----------------
__device__ __nv_bfloat16 g_ah[(size_t)NTOT * DD];   // agg hi (bf16)
__device__ __nv_bfloat16 g_al[(size_t)NTOT * DD];   // agg lo (bf16)
__device__ float g_o[(size_t)NTOT * DD];            // relu(conv output)
__device__ float g_dinv[NTOT];
__device__ float g_scorep[2 * NTOT];                // per-half score partials
__device__ float g_w[NTOT];                         // pooling weights (tanh or 0)
__device__ float g_pinv;
__device__ int   g_off[NTOT + 1];
__device__ int2  g_epack[ETOT];                     // {src_local, norm bits} by dst

// ========== fused per-graph CSR build + (block 0) p-norm ==========
__global__ __launch_bounds__(512) void k_build(const int* __restrict__ ei,
                                               const float* __restrict__ ew,
                                               const float* __restrict__ p) {
    __shared__ float sdeg[NPG];
    __shared__ int   scnt[NPG];
    __shared__ int   soff[NPG];
    __shared__ int   scur[NPG];
    __shared__ int   s2[512];

    int g = blockIdx.x;
    int t = threadIdx.x;
    int base_e = g * EPG;
    int base_n = g * NPG;
    const int* src = ei;
    const int* dst = ei + ETOT;

    if (g == 0 && t < 32) {
        float4 pv = ((const float4*)p)[t];
        float pp = pv.x * pv.x + pv.y * pv.y + pv.z * pv.z + pv.w * pv.w;
        #pragma unroll
        for (int off = 16; off > 0; off >>= 1) pp += __shfl_xor_sync(0xFFFFFFFFu, pp, off);
        if (t == 0) g_pinv = rsqrtf(pp);
    }

    #pragma unroll
    for (int i = t; i < NPG; i += 512) { sdeg[i] = 1.0f; scnt[i] = 0; }
    __syncthreads();

    for (int e = t; e < EPG; e += 512) {
        int d = dst[base_e + e] - base_n;
        atomicAdd(&sdeg[d], ew[base_e + e]);
        atomicAdd(&scnt[d], 1);
    }
    __syncthreads();

    #pragma unroll
    for (int i = t; i < NPG; i += 512)
        sdeg[i] = rsqrtf(fmaxf(sdeg[i], 1e-12f));
    __syncthreads();

    int c0 = scnt[2 * t], c1 = scnt[2 * t + 1];
    int pairsum = c0 + c1;
    s2[t] = pairsum;
    __syncthreads();
    for (int d = 1; d < 512; d <<= 1) {
        int u = (t >= d) ? s2[t - d] : 0;
        __syncthreads(); s2[t] += u; __syncthreads();
    }
    int excl = s2[t] - pairsum;
    soff[2 * t]     = excl;
    soff[2 * t + 1] = excl + c0;
    scur[2 * t]     = excl;
    scur[2 * t + 1] = excl + c0;
    __syncthreads();

    #pragma unroll
    for (int i = t; i < NPG; i += 512) {
        g_dinv[base_n + i] = sdeg[i];
        g_off[base_n + i]  = base_e + soff[i];
    }
    if (g == 0 && t == 0) g_off[NTOT] = ETOT;

    for (int e = t; e < EPG; e += 512) {
        int s = src[base_e + e] - base_n;
        int d = dst[base_e + e] - base_n;
        float nrm = sdeg[s] * ew[base_e + e] * sdeg[d];
        int pos = atomicAdd(&scur[d], 1);
        g_epack[base_e + pos] = make_int2(s, __float_as_int(nrm));
    }
}

// ========== gather: warp per node, coalesced epack + shfl; bf16 hi/lo output ==========
__global__ void k_gather(const float* __restrict__ x) {
    int gt   = blockIdx.x * blockDim.x + threadIdx.x;
    int node = gt >> 5;
    int lane = gt & 31;
    if (node >= NTOT) return;
    int base_n = node & ~(NPG - 1);

    const float4* x4 = (const float4*)x;
    float di = g_dinv[node];
    float c  = di * di;
    float4 xv = x4[(size_t)node * 32 + lane];
    float4 acc = make_float4(c * xv.x, c * xv.y, c * xv.z, c * xv.w);

    int i0 = g_off[node], i1 = g_off[node + 1];
    for (int base = i0; base < i1; base += 32) {
        int nload = i1 - base; if (nload > 32) nload = 32;
        int2 pk = make_int2(0, 0);
        if (lane < nload) pk = g_epack[base + lane];
        int j = 0;
        for (; j + 4 <= nload; j += 4) {
            #pragma unroll
            for (int u = 0; u < 4; u++) {
                int   s  = base_n + __shfl_sync(0xFFFFFFFFu, pk.x, j + u);
                float nm = __int_as_float(__shfl_sync(0xFFFFFFFFu, pk.y, j + u));
                float4 v = x4[(size_t)s * 32 + lane];
                acc.x += nm * v.x; acc.y += nm * v.y;
                acc.z += nm * v.z; acc.w += nm * v.w;
            }
        }
        for (; j < nload; j++) {
            int   s  = base_n + __shfl_sync(0xFFFFFFFFu, pk.x, j);
            float nm = __int_as_float(__shfl_sync(0xFFFFFFFFu, pk.y, j));
            float4 v = x4[(size_t)s * 32 + lane];
            acc.x += nm * v.x; acc.y += nm * v.y;
            acc.z += nm * v.z; acc.w += nm * v.w;
        }
    }

    // bf16 hi/lo split (exact same rounding as fp32->split in GEMM would give)
    float a[4] = {acc.x, acc.y, acc.z, acc.w};
    __nv_bfloat16 hi[4], lo[4];
    #pragma unroll
    for (int j = 0; j < 4; j++) {
        hi[j] = __float2bfloat16_rn(a[j]);
        lo[j] = __float2bfloat16_rn(a[j] - __bfloat162float(hi[j]));
    }
    size_t off = (size_t)node * DD + lane * 4;
    *(uint2*)&g_ah[off] = *(uint2*)hi;
    *(uint2*)&g_al[off] = *(uint2*)lo;
}

// ========== tensor-core GEMM (pre-split A), N-split for 2 CTAs/SM ==========
#define AP 136                                  // pitch: 272B rows -> conflict-free frags
#define NH 64
#define SM_A_HI 0
#define SM_A_LO (128 * AP)
#define SM_B_HI (2 * 128 * AP)
#define SM_B_LO (2 * 128 * AP + NH * AP)
#define SM_F_OFF ((2 * 128 + 2 * NH) * AP * 2)
#define GTC_SMEM (SM_F_OFF + 2 * NH * 4)

__device__ __forceinline__ void bf16_split(float v, __nv_bfloat16& hi, __nv_bfloat16& lo) {
    hi = __float2bfloat16_rn(v);
    lo = __float2bfloat16_rn(v - __bfloat162float(hi));
}

__device__ __forceinline__ void mma_bf16(float* c, uint32_t a0, uint32_t a1, uint32_t a2,
                                         uint32_t a3, uint32_t b0, uint32_t b1) {
    asm volatile(
        "mma.sync.aligned.m16n8k16.row.col.f32.bf16.bf16.f32 "
        "{%0,%1,%2,%3}, {%4,%5,%6,%7}, {%8,%9}, {%0,%1,%2,%3};"
        : "+f"(c[0]), "+f"(c[1]), "+f"(c[2]), "+f"(c[3])
        : "r"(a0), "r"(a1), "r"(a2), "r"(a3), "r"(b0), "r"(b1));
}

__global__ __launch_bounds__(256, 2) void k_gemm_mma(const float* __restrict__ W,
                                                     const float* __restrict__ bvec,
                                                     const float* __restrict__ pvec) {
    extern __shared__ __nv_bfloat16 smb[];
    __nv_bfloat16* Ah = smb + SM_A_HI;
    __nv_bfloat16* Al = smb + SM_A_LO;
    __nv_bfloat16* Bh = smb + SM_B_HI;
    __nv_bfloat16* Bl = smb + SM_B_LO;
    float* bs = (float*)((char*)smb + SM_F_OFF);
    float* ps = bs + NH;

    int tid = threadIdx.x;
    int rb  = (blockIdx.x >> 1) * 128;
    int nh  = blockIdx.x & 1;

    // stage A: plain uint4 copies of pre-split bf16 (8 bf16 per load)
    for (int i = tid; i < 128 * 16; i += 256) {
        int r = i >> 4, q = i & 15;                 // q: 8-elem chunk
        size_t src = (size_t)(rb + r) * DD + q * 8;
        *(uint4*)&Ah[r * AP + q * 8] = *(const uint4*)&g_ah[src];
        *(uint4*)&Al[r * AP + q * 8] = *(const uint4*)&g_al[src];
    }
    // stage B-half = W^T rows [nh*64, nh*64+64), split on the fly (small)
    for (int i = tid; i < 128 * 16; i += 256) {
        int k = i >> 4, q = i & 15;
        float4 v = *(const float4*)&W[(size_t)k * DD + nh * NH + q * 4];
        float vv[4] = {v.x, v.y, v.z, v.w};
        #pragma unroll
        for (int j = 0; j < 4; j++) {
            __nv_bfloat16 hi, lo;
            bf16_split(vv[j], hi, lo);
            Bh[(q * 4 + j) * AP + k] = hi;
            Bl[(q * 4 + j) * AP + k] = lo;
        }
    }
    if (tid < NH) { bs[tid] = bvec[nh * NH + tid]; ps[tid] = pvec[nh * NH + tid]; }
    __syncthreads();

    int w  = tid >> 5;
    int l  = tid & 31;
    int qr = l >> 2;
    int qc = l & 3;

    float acc[8][4];
    #pragma unroll
    for (int t = 0; t < 8; t++)
        #pragma unroll
        for (int j = 0; j < 4; j++) acc[t][j] = 0.0f;

    const __nv_bfloat16* arow0  = Ah + (w * 16 + qr) * AP;
    const __nv_bfloat16* arow1  = arow0 + 8 * AP;
    const __nv_bfloat16* alrow0 = Al + (w * 16 + qr) * AP;
    const __nv_bfloat16* alrow1 = alrow0 + 8 * AP;

    #pragma unroll
    for (int ks = 0; ks < 8; ks++) {
        int k0 = ks * 16;
        uint32_t ah0 = *(const uint32_t*)(arow0  + k0 + qc * 2);
        uint32_t ah1 = *(const uint32_t*)(arow1  + k0 + qc * 2);
        uint32_t ah2 = *(const uint32_t*)(arow0  + k0 + 8 + qc * 2);
        uint32_t ah3 = *(const uint32_t*)(arow1  + k0 + 8 + qc * 2);
        uint32_t al0 = *(const uint32_t*)(alrow0 + k0 + qc * 2);
        uint32_t al1 = *(const uint32_t*)(alrow1 + k0 + qc * 2);
        uint32_t al2 = *(const uint32_t*)(alrow0 + k0 + 8 + qc * 2);
        uint32_t al3 = *(const uint32_t*)(alrow1 + k0 + 8 + qc * 2);

        #pragma unroll
        for (int t = 0; t < 8; t++) {
            const __nv_bfloat16* brow  = Bh + (t * 8 + qr) * AP;
            const __nv_bfloat16* browl = Bl + (t * 8 + qr) * AP;
            uint32_t bh0 = *(const uint32_t*)(brow  + k0 + qc * 2);
            uint32_t bh1 = *(const uint32_t*)(brow  + k0 + 8 + qc * 2);
            uint32_t bl0 = *(const uint32_t*)(browl + k0 + qc * 2);
            uint32_t bl1 = *(const uint32_t*)(browl + k0 + 8 + qc * 2);
            mma_bf16(acc[t], ah0, ah1, ah2, ah3, bh0, bh1);
            mma_bf16(acc[t], ah0, ah1, ah2, ah3, bl0, bl1);
            mma_bf16(acc[t], al0, al1, al2, al3, bh0, bh1);
        }
    }

    int r0 = rb + w * 16 + qr;
    int r1 = r0 + 8;
    float s0 = 0.0f, s1 = 0.0f;
    #pragma unroll
    for (int t = 0; t < 8; t++) {
        int cl = t * 8 + qc * 2;
        int cg = nh * NH + cl;
        float b0 = bs[cl], b1 = bs[cl + 1];
        float p0 = ps[cl], p1 = ps[cl + 1];
        float v00 = fmaxf(acc[t][0] + b0, 0.0f);
        float v01 = fmaxf(acc[t][1] + b1, 0.0f);
        float v10 = fmaxf(acc[t][2] + b0, 0.0f);
        float v11 = fmaxf(acc[t][3] + b1, 0.0f);
        *(float2*)&g_o[(size_t)r0 * DD + cg] = make_float2(v00, v01);
        *(float2*)&g_o[(size_t)r1 * DD + cg] = make_float2(v10, v11);
        s0 += v00 * p0 + v01 * p1;
        s1 += v10 * p0 + v11 * p1;
    }
    s0 += __shfl_xor_sync(0xFFFFFFFFu, s0, 1);
    s0 += __shfl_xor_sync(0xFFFFFFFFu, s0, 2);
    s1 += __shfl_xor_sync(0xFFFFFFFFu, s1, 1);
    s1 += __shfl_xor_sync(0xFFFFFFFFu, s1, 2);
    if (qc == 0) {
        g_scorep[2 * r0 + nh] = s0;
        g_scorep[2 * r1 + nh] = s1;
    }
}

// ========== select: radix threshold (warp-level suffix scan) -> weights ==========
__global__ void k_select() {
    __shared__ uint32_t s_u[NPG];
    __shared__ int      hist[256];
    __shared__ int      sB, sRem;

    int g = blockIdx.x;
    int t = threadIdx.x;
    int base = g * NPG;

    float sc = (g_scorep[2 * (base + t)] + g_scorep[2 * (base + t) + 1]) * g_pinv;
    uint32_t u = __float_as_uint(sc);
    u = (u & 0x80000000u) ? ~u : (u | 0x80000000u);
    s_u[t] = u;

    bool active = true, sel_gt = false;
    int remaining = KK;

    #pragma unroll
    for (int shift = 24; shift >= 0; shift -= 8) {
        if (t < 256) hist[t] = 0;
        __syncthreads();
        int mybin = (int)((u >> shift) & 0xFFu);
        if (active) atomicAdd(&hist[mybin], 1);
        __syncthreads();

        if (t < 32) {   // warp 0: suffix counts + threshold pick, no block barriers
            int v[8], chunk = 0;
            #pragma unroll
            for (int j = 0; j < 8; j++) { v[j] = hist[t * 8 + j]; chunk += v[j]; }
            int run = chunk;   // inclusive suffix over lanes
            #pragma unroll
            for (int o = 1; o < 32; o <<= 1) {
                int uu = __shfl_down_sync(0xFFFFFFFFu, run, o);
                if (t + o < 32) run += uu;
            }
            int s[9];
            s[8] = run - chunk;             // suffix above my chunk
            #pragma unroll
            for (int j = 7; j >= 0; j--) s[j] = s[j + 1] + v[j];
            #pragma unroll
            for (int j = 0; j < 8; j++) {
                if (s[j] >= remaining && s[j + 1] < remaining) {
                    sB = t * 8 + j;
                    sRem = remaining - s[j + 1];
                }
            }
        }
        __syncthreads();
        int B = sB; remaining = sRem;
        if (active) {
            if (mybin > B) { sel_gt = true; active = false; }
            else if (mybin < B) active = false;
        }
        __syncthreads();
    }

    float wgt = 0.0f;
    if (sel_gt) {
        wgt = tanhf(sc);
    } else if (active) {
        uint32_t uth = u;
        int r = 0;
        for (int j = 0; j < t; j++) if (s_u[j] == uth) r++;
        if (r < remaining) wgt = tanhf(sc);
    }
    g_w[base + t] = wgt;
}

// ========== weighted sum: block = (graph, 32-col quarter) ==========
__global__ __launch_bounds__(512) void k_wsum(float* __restrict__ out) {
    __shared__ float s_w[NPG];
    __shared__ float s_part[16 * 32];

    int g = blockIdx.x >> 2;
    int q = blockIdx.x & 3;
    int base = g * NPG;
    int t = threadIdx.x;
    int lane = t & 31;
    int grp  = t >> 5;

    for (int i = t; i < NPG; i += 512) s_w[i] = g_w[base + i];
    __syncthreads();

    float part = 0.0f;
    #pragma unroll 4
    for (int n = grp; n < NPG; n += 16) {
        float wn = s_w[n];
        if (wn != 0.0f)
            part += wn * g_o[(size_t)(base + n) * DD + q * 32 + lane];
    }
    s_part[grp * 32 + lane] = part;
    __syncthreads();

    if (t < 32) {
        float s = 0.0f;
        #pragma unroll
        for (int r = 0; r < 16; r++) s += s_part[r * 32 + t];
        out[g * DD + q * 32 + t] = s * (1.0f / (float)KK);
    }
}

// ---------------- launch ----------------
extern "C" void kernel_launch(void* const* d_in, const int* in_sizes, int n_in,
                              void* d_out, int out_size) {
    const float* x  = (const float*)d_in[0];
    const float* ew = (const float*)d_in[1];
    const float* W  = (const float*)d_in[2];
    const float* b  = (const float*)d_in[3];
    const float* p  = (const float*)d_in[4];
    const int*   ei = (const int*)d_in[5];
    float* out = (float*)d_out;

    static int s_attr_done = 0;
    if (!s_attr_done) {
        cudaFuncSetAttribute(k_gemm_mma, cudaFuncAttributeMaxDynamicSharedMemorySize, GTC_SMEM);
        s_attr_done = 1;
    }

    k_build<<<BG, 512>>>(ei, ew, p);
    k_gather<<<(NTOT * 32) / 256, 256>>>(x);
    k_gemm_mma<<<(NTOT / 128) * 2, 256, GTC_SMEM>>>(W, b, p);
    k_select<<<BG, NPG>>>();
    k_wsum<<<BG * 4, 512>>>(out);
}

// round 10
// speedup vs baseline: 2.0000x; 1.0276x over previous
#include <cuda_runtime.h>
#include <cuda_bf16.h>
#include <cstdint>
#include <math.h>

#define NTOT 65536
#define BG   64
#define NPG  1024
#define ETOT 1048576
#define EPG  (ETOT / BG)     // 16384 edges per graph
#define DD   128
#define KK   512             // NPG/2

// ---------------- scratch (device globals: allocation-free) ----------------
__device__ __nv_bfloat16 g_ah[(size_t)NTOT * DD];   // agg hi (bf16)
__device__ __nv_bfloat16 g_al[(size_t)NTOT * DD];   // agg lo (bf16)
__device__ float g_o[(size_t)NTOT * DD];            // relu(conv output)
__device__ float g_dinv[NTOT];
__device__ float g_scorep[2 * NTOT];                // per-half score partials
__device__ float g_pinv;
__device__ int   g_off[NTOT + 1];
__device__ int2  g_epack[ETOT];                     // {src_local, norm bits} by dst

// ========== fused per-graph CSR build + (block 0) p-norm ==========
__global__ __launch_bounds__(512) void k_build(const int* __restrict__ ei,
                                               const float* __restrict__ ew,
                                               const float* __restrict__ p) {
    __shared__ float sdeg[NPG];
    __shared__ int   scnt[NPG];
    __shared__ int   soff[NPG];
    __shared__ int   scur[NPG];
    __shared__ int   s2[512];

    int g = blockIdx.x;
    int t = threadIdx.x;
    int base_e = g * EPG;
    int base_n = g * NPG;
    const int* src = ei;
    const int* dst = ei + ETOT;

    if (g == 0 && t < 32) {
        float4 pv = ((const float4*)p)[t];
        float pp = pv.x * pv.x + pv.y * pv.y + pv.z * pv.z + pv.w * pv.w;
        #pragma unroll
        for (int off = 16; off > 0; off >>= 1) pp += __shfl_xor_sync(0xFFFFFFFFu, pp, off);
        if (t == 0) g_pinv = rsqrtf(pp);
    }

    #pragma unroll
    for (int i = t; i < NPG; i += 512) { sdeg[i] = 1.0f; scnt[i] = 0; }
    __syncthreads();

    for (int e = t; e < EPG; e += 512) {
        int d = dst[base_e + e] - base_n;
        atomicAdd(&sdeg[d], ew[base_e + e]);
        atomicAdd(&scnt[d], 1);
    }
    __syncthreads();

    #pragma unroll
    for (int i = t; i < NPG; i += 512)
        sdeg[i] = rsqrtf(fmaxf(sdeg[i], 1e-12f));
    __syncthreads();

    int c0 = scnt[2 * t], c1 = scnt[2 * t + 1];
    int pairsum = c0 + c1;
    s2[t] = pairsum;
    __syncthreads();
    for (int d = 1; d < 512; d <<= 1) {
        int u = (t >= d) ? s2[t - d] : 0;
        __syncthreads(); s2[t] += u; __syncthreads();
    }
    int excl = s2[t] - pairsum;
    soff[2 * t]     = excl;
    soff[2 * t + 1] = excl + c0;
    scur[2 * t]     = excl;
    scur[2 * t + 1] = excl + c0;
    __syncthreads();

    #pragma unroll
    for (int i = t; i < NPG; i += 512) {
        g_dinv[base_n + i] = sdeg[i];
        g_off[base_n + i]  = base_e + soff[i];
    }
    if (g == 0 && t == 0) g_off[NTOT] = ETOT;

    for (int e = t; e < EPG; e += 512) {
        int s = src[base_e + e] - base_n;
        int d = dst[base_e + e] - base_n;
        float nrm = sdeg[s] * ew[base_e + e] * sdeg[d];
        int pos = atomicAdd(&scur[d], 1);
        g_epack[base_e + pos] = make_int2(s, __float_as_int(nrm));
    }
}

// ========== gather: warp per node, coalesced epack + shfl; bf16 hi/lo output ==========
__global__ void k_gather(const float* __restrict__ x) {
    int gt   = blockIdx.x * blockDim.x + threadIdx.x;
    int node = gt >> 5;
    int lane = gt & 31;
    if (node >= NTOT) return;
    int base_n = node & ~(NPG - 1);

    const float4* x4 = (const float4*)x;
    float di = g_dinv[node];
    float c  = di * di;
    float4 xv = x4[(size_t)node * 32 + lane];
    float4 acc = make_float4(c * xv.x, c * xv.y, c * xv.z, c * xv.w);

    int i0 = g_off[node], i1 = g_off[node + 1];
    for (int base = i0; base < i1; base += 32) {
        int nload = i1 - base; if (nload > 32) nload = 32;
        int2 pk = make_int2(0, 0);
        if (lane < nload) pk = g_epack[base + lane];
        int j = 0;
        for (; j + 4 <= nload; j += 4) {
            #pragma unroll
            for (int u = 0; u < 4; u++) {
                int   s  = base_n + __shfl_sync(0xFFFFFFFFu, pk.x, j + u);
                float nm = __int_as_float(__shfl_sync(0xFFFFFFFFu, pk.y, j + u));
                float4 v = x4[(size_t)s * 32 + lane];
                acc.x += nm * v.x; acc.y += nm * v.y;
                acc.z += nm * v.z; acc.w += nm * v.w;
            }
        }
        for (; j < nload; j++) {
            int   s  = base_n + __shfl_sync(0xFFFFFFFFu, pk.x, j);
            float nm = __int_as_float(__shfl_sync(0xFFFFFFFFu, pk.y, j));
            float4 v = x4[(size_t)s * 32 + lane];
            acc.x += nm * v.x; acc.y += nm * v.y;
            acc.z += nm * v.z; acc.w += nm * v.w;
        }
    }

    float a[4] = {acc.x, acc.y, acc.z, acc.w};
    __nv_bfloat16 hi[4], lo[4];
    #pragma unroll
    for (int j = 0; j < 4; j++) {
        hi[j] = __float2bfloat16_rn(a[j]);
        lo[j] = __float2bfloat16_rn(a[j] - __bfloat162float(hi[j]));
    }
    size_t off = (size_t)node * DD + lane * 4;
    *(uint2*)&g_ah[off] = *(uint2*)hi;
    *(uint2*)&g_al[off] = *(uint2*)lo;
}

// ========== tensor-core GEMM (pre-split A), N-split for 2 CTAs/SM ==========
#define AP 136
#define NH 64
#define SM_A_HI 0
#define SM_A_LO (128 * AP)
#define SM_B_HI (2 * 128 * AP)
#define SM_B_LO (2 * 128 * AP + NH * AP)
#define SM_F_OFF ((2 * 128 + 2 * NH) * AP * 2)
#define GTC_SMEM (SM_F_OFF + 2 * NH * 4)

__device__ __forceinline__ void bf16_split(float v, __nv_bfloat16& hi, __nv_bfloat16& lo) {
    hi = __float2bfloat16_rn(v);
    lo = __float2bfloat16_rn(v - __bfloat162float(hi));
}

__device__ __forceinline__ void mma_bf16(float* c, uint32_t a0, uint32_t a1, uint32_t a2,
                                         uint32_t a3, uint32_t b0, uint32_t b1) {
    asm volatile(
        "mma.sync.aligned.m16n8k16.row.col.f32.bf16.bf16.f32 "
        "{%0,%1,%2,%3}, {%4,%5,%6,%7}, {%8,%9}, {%0,%1,%2,%3};"
        : "+f"(c[0]), "+f"(c[1]), "+f"(c[2]), "+f"(c[3])
        : "r"(a0), "r"(a1), "r"(a2), "r"(a3), "r"(b0), "r"(b1));
}

__global__ __launch_bounds__(256, 2) void k_gemm_mma(const float* __restrict__ W,
                                                     const float* __restrict__ bvec,
                                                     const float* __restrict__ pvec) {
    extern __shared__ __nv_bfloat16 smb[];
    __nv_bfloat16* Ah = smb + SM_A_HI;
    __nv_bfloat16* Al = smb + SM_A_LO;
    __nv_bfloat16* Bh = smb + SM_B_HI;
    __nv_bfloat16* Bl = smb + SM_B_LO;
    float* bs = (float*)((char*)smb + SM_F_OFF);
    float* ps = bs + NH;

    int tid = threadIdx.x;
    int rb  = (blockIdx.x >> 1) * 128;
    int nh  = blockIdx.x & 1;

    for (int i = tid; i < 128 * 16; i += 256) {
        int r = i >> 4, q = i & 15;
        size_t src = (size_t)(rb + r) * DD + q * 8;
        *(uint4*)&Ah[r * AP + q * 8] = *(const uint4*)&g_ah[src];
        *(uint4*)&Al[r * AP + q * 8] = *(const uint4*)&g_al[src];
    }
    for (int i = tid; i < 128 * 16; i += 256) {
        int k = i >> 4, q = i & 15;
        float4 v = *(const float4*)&W[(size_t)k * DD + nh * NH + q * 4];
        float vv[4] = {v.x, v.y, v.z, v.w};
        #pragma unroll
        for (int j = 0; j < 4; j++) {
            __nv_bfloat16 hi, lo;
            bf16_split(vv[j], hi, lo);
            Bh[(q * 4 + j) * AP + k] = hi;
            Bl[(q * 4 + j) * AP + k] = lo;
        }
    }
    if (tid < NH) { bs[tid] = bvec[nh * NH + tid]; ps[tid] = pvec[nh * NH + tid]; }
    __syncthreads();

    int w  = tid >> 5;
    int l  = tid & 31;
    int qr = l >> 2;
    int qc = l & 3;

    float acc[8][4];
    #pragma unroll
    for (int t = 0; t < 8; t++)
        #pragma unroll
        for (int j = 0; j < 4; j++) acc[t][j] = 0.0f;

    const __nv_bfloat16* arow0  = Ah + (w * 16 + qr) * AP;
    const __nv_bfloat16* arow1  = arow0 + 8 * AP;
    const __nv_bfloat16* alrow0 = Al + (w * 16 + qr) * AP;
    const __nv_bfloat16* alrow1 = alrow0 + 8 * AP;

    #pragma unroll
    for (int ks = 0; ks < 8; ks++) {
        int k0 = ks * 16;
        uint32_t ah0 = *(const uint32_t*)(arow0  + k0 + qc * 2);
        uint32_t ah1 = *(const uint32_t*)(arow1  + k0 + qc * 2);
        uint32_t ah2 = *(const uint32_t*)(arow0  + k0 + 8 + qc * 2);
        uint32_t ah3 = *(const uint32_t*)(arow1  + k0 + 8 + qc * 2);
        uint32_t al0 = *(const uint32_t*)(alrow0 + k0 + qc * 2);
        uint32_t al1 = *(const uint32_t*)(alrow1 + k0 + qc * 2);
        uint32_t al2 = *(const uint32_t*)(alrow0 + k0 + 8 + qc * 2);
        uint32_t al3 = *(const uint32_t*)(alrow1 + k0 + 8 + qc * 2);

        #pragma unroll
        for (int t = 0; t < 8; t++) {
            const __nv_bfloat16* brow  = Bh + (t * 8 + qr) * AP;
            const __nv_bfloat16* browl = Bl + (t * 8 + qr) * AP;
            uint32_t bh0 = *(const uint32_t*)(brow  + k0 + qc * 2);
            uint32_t bh1 = *(const uint32_t*)(brow  + k0 + 8 + qc * 2);
            uint32_t bl0 = *(const uint32_t*)(browl + k0 + qc * 2);
            uint32_t bl1 = *(const uint32_t*)(browl + k0 + 8 + qc * 2);
            mma_bf16(acc[t], ah0, ah1, ah2, ah3, bh0, bh1);
            mma_bf16(acc[t], ah0, ah1, ah2, ah3, bl0, bl1);
            mma_bf16(acc[t], al0, al1, al2, al3, bh0, bh1);
        }
    }

    int r0 = rb + w * 16 + qr;
    int r1 = r0 + 8;
    float s0 = 0.0f, s1 = 0.0f;
    #pragma unroll
    for (int t = 0; t < 8; t++) {
        int cl = t * 8 + qc * 2;
        int cg = nh * NH + cl;
        float b0 = bs[cl], b1 = bs[cl + 1];
        float p0 = ps[cl], p1 = ps[cl + 1];
        float v00 = fmaxf(acc[t][0] + b0, 0.0f);
        float v01 = fmaxf(acc[t][1] + b1, 0.0f);
        float v10 = fmaxf(acc[t][2] + b0, 0.0f);
        float v11 = fmaxf(acc[t][3] + b1, 0.0f);
        *(float2*)&g_o[(size_t)r0 * DD + cg] = make_float2(v00, v01);
        *(float2*)&g_o[(size_t)r1 * DD + cg] = make_float2(v10, v11);
        s0 += v00 * p0 + v01 * p1;
        s1 += v10 * p0 + v11 * p1;
    }
    s0 += __shfl_xor_sync(0xFFFFFFFFu, s0, 1);
    s0 += __shfl_xor_sync(0xFFFFFFFFu, s0, 2);
    s1 += __shfl_xor_sync(0xFFFFFFFFu, s1, 1);
    s1 += __shfl_xor_sync(0xFFFFFFFFu, s1, 2);
    if (qc == 0) {
        g_scorep[2 * r0 + nh] = s0;
        g_scorep[2 * r1 + nh] = s1;
    }
}

// ========== fused pool: per-block radix select (redundant x4) + weighted sum ==========
// block = (graph, 32-col quarter); 512 threads, 2 scores per thread
__global__ __launch_bounds__(512) void k_pool(float* __restrict__ out) {
    __shared__ uint32_t s_u[NPG];
    __shared__ float    s_sc[NPG];
    __shared__ float    s_w[NPG];
    __shared__ int      hist[256];
    __shared__ int      sB, sRem;
    __shared__ float    s_part[16 * 32];

    int g = blockIdx.x >> 2;
    int q = blockIdx.x & 3;
    int base = g * NPG;
    int t = threadIdx.x;

    // load two scores per thread
    float sc[2]; uint32_t u[2];
    #pragma unroll
    for (int j = 0; j < 2; j++) {
        int n = 2 * t + j;
        float v = (g_scorep[2 * (base + n)] + g_scorep[2 * (base + n) + 1]) * g_pinv;
        sc[j] = v;
        uint32_t b = __float_as_uint(v);
        b = (b & 0x80000000u) ? ~b : (b | 0x80000000u);
        u[j] = b;
        s_u[n] = b; s_sc[n] = v;
    }

    bool act[2] = {true, true}, gtS[2] = {false, false};
    int remaining = KK;

    #pragma unroll
    for (int shift = 24; shift >= 0; shift -= 8) {
        if (t < 256) hist[t] = 0;
        __syncthreads();
        int bin[2];
        #pragma unroll
        for (int j = 0; j < 2; j++) {
            bin[j] = (int)((u[j] >> shift) & 0xFFu);
            if (act[j]) atomicAdd(&hist[bin[j]], 1);
        }
        __syncthreads();
        if (t < 32) {   // warp 0: suffix scan + threshold pick
            int v[8], chunk = 0;
            #pragma unroll
            for (int j = 0; j < 8; j++) { v[j] = hist[t * 8 + j]; chunk += v[j]; }
            int run = chunk;
            #pragma unroll
            for (int o = 1; o < 32; o <<= 1) {
                int uu = __shfl_down_sync(0xFFFFFFFFu, run, o);
                if (t + o < 32) run += uu;
            }
            int s[9];
            s[8] = run - chunk;
            #pragma unroll
            for (int j = 7; j >= 0; j--) s[j] = s[j + 1] + v[j];
            #pragma unroll
            for (int j = 0; j < 8; j++) {
                if (s[j] >= remaining && s[j + 1] < remaining) {
                    sB = t * 8 + j;
                    sRem = remaining - s[j + 1];
                }
            }
        }
        __syncthreads();
        int B = sB; remaining = sRem;
        #pragma unroll
        for (int j = 0; j < 2; j++) {
            if (act[j]) {
                if (bin[j] > B) { gtS[j] = true; act[j] = false; }
                else if (bin[j] < B) act[j] = false;
            }
        }
        __syncthreads();
    }

    #pragma unroll
    for (int j = 0; j < 2; j++) {
        int n = 2 * t + j;
        float wgt = 0.0f;
        if (gtS[j]) {
            wgt = tanhf(sc[j]);
        } else if (act[j]) {
            uint32_t uth = u[j];
            int r = 0;
            for (int jj = 0; jj < n; jj++) if (s_u[jj] == uth) r++;
            if (r < remaining) wgt = tanhf(sc[j]);
        }
        s_w[n] = wgt;
    }
    __syncthreads();

    // weighted sum over this block's 32-col quarter
    int lane = t & 31;
    int grp  = t >> 5;        // 0..15
    float part = 0.0f;
    #pragma unroll 4
    for (int n = grp; n < NPG; n += 16) {
        float wn = s_w[n];
        if (wn != 0.0f)
            part += wn * g_o[(size_t)(base + n) * DD + q * 32 + lane];
    }
    s_part[grp * 32 + lane] = part;
    __syncthreads();

    if (t < 32) {
        float s = 0.0f;
        #pragma unroll
        for (int r = 0; r < 16; r++) s += s_part[r * 32 + t];
        out[g * DD + q * 32 + t] = s * (1.0f / (float)KK);
    }
}

// ---------------- launch ----------------
extern "C" void kernel_launch(void* const* d_in, const int* in_sizes, int n_in,
                              void* d_out, int out_size) {
    const float* x  = (const float*)d_in[0];
    const float* ew = (const float*)d_in[1];
    const float* W  = (const float*)d_in[2];
    const float* b  = (const float*)d_in[3];
    const float* p  = (const float*)d_in[4];
    const int*   ei = (const int*)d_in[5];
    float* out = (float*)d_out;

    static int s_attr_done = 0;
    if (!s_attr_done) {
        cudaFuncSetAttribute(k_gemm_mma, cudaFuncAttributeMaxDynamicSharedMemorySize, GTC_SMEM);
        s_attr_done = 1;
    }

    k_build<<<BG, 512>>>(ei, ew, p);
    k_gather<<<(NTOT * 32) / 256, 256>>>(x);
    k_gemm_mma<<<(NTOT / 128) * 2, 256, GTC_SMEM>>>(W, b, p);
    k_pool<<<BG * 4, 512>>>(out);
}